// round 9
// baseline (speedup 1.0000x reference)
#include <cuda_runtime.h>
#include <cstdint>

#define B_  8
#define T_  2048
#define E_  1024
#define H_  64
#define BT_ (B_ * T_)

typedef unsigned int u32;
typedef unsigned short u16;

// fp16 scratch (static device arrays; no runtime alloc)
__device__ u16 g_w16[3 * E_ * H_];   // W fp16 [m][e][n]
__device__ u16 g_q16[BT_ * H_];      // [t][h] (scaled 1/32)
__device__ u16 g_k16[BT_ * H_];      // [b][h][t] (transposed)
__device__ u16 g_v16[BT_ * H_];      // [t][h]

// ---------------------------------------------------------------------------
__device__ __forceinline__ u32 smem_u32(const void* p) {
    u32 a;
    asm("{ .reg .u64 t; cvta.to.shared.u64 t, %1; cvt.u32.u64 %0, t; }"
        : "=r"(a) : "l"(p));
    return a;
}
__device__ __forceinline__ u32 swa(u32 base, int r, int c) {
    return base + r * 128 + (((c ^ (r & 7)) & 7) << 4);
}
__device__ __forceinline__ float fast_exp2(float x) {
    float y;
    asm("ex2.approx.ftz.f32 %0, %1;" : "=f"(y) : "f"(x));
    return y;
}
__device__ __forceinline__ u32 cvt2h(float a, float b) {
    u32 r;
    asm("cvt.rn.f16x2.f32 %0, %1, %2;" : "=r"(r) : "f"(b), "f"(a));
    return r;
}
__device__ __forceinline__ u16 h16(float a) {
    u16 r;
    asm("cvt.rn.f16.f32 %0, %1;" : "=h"(r) : "f"(a));
    return r;
}
__device__ __forceinline__ void ldsm4(u32& r0, u32& r1, u32& r2, u32& r3, u32 a) {
    asm volatile("ldmatrix.sync.aligned.m8n8.x4.shared.b16 {%0,%1,%2,%3}, [%4];"
                 : "=r"(r0), "=r"(r1), "=r"(r2), "=r"(r3) : "r"(a));
}
__device__ __forceinline__ void ldsm4t(u32& r0, u32& r1, u32& r2, u32& r3, u32 a) {
    asm volatile("ldmatrix.sync.aligned.m8n8.x4.trans.shared.b16 {%0,%1,%2,%3}, [%4];"
                 : "=r"(r0), "=r"(r1), "=r"(r2), "=r"(r3) : "r"(a));
}
__device__ __forceinline__ void mma16816(float* c, const u32* a, u32 b0, u32 b1) {
    asm volatile(
        "mma.sync.aligned.m16n8k16.row.col.f32.f16.f16.f32 "
        "{%0,%1,%2,%3}, {%4,%5,%6,%7}, {%8,%9}, {%0,%1,%2,%3};"
        : "+f"(c[0]), "+f"(c[1]), "+f"(c[2]), "+f"(c[3])
        : "r"(a[0]), "r"(a[1]), "r"(a[2]), "r"(a[3]), "r"(b0), "r"(b1));
}
__device__ __forceinline__ void cpa16(u32 s, const void* g) {
    asm volatile("cp.async.cg.shared.global [%0], [%1], 16;" :: "r"(s), "l"(g));
}
#define CP_COMMIT() asm volatile("cp.async.commit_group;" ::: "memory")
#define CP_WAIT0()  asm volatile("cp.async.wait_group 0;" ::: "memory")

// ---------------------------------------------------------------------------
__global__ void __launch_bounds__(256) prep_w_kernel(
    const float* __restrict__ Wk, const float* __restrict__ Wq,
    const float* __restrict__ Wv)
{
    int idx = blockIdx.x * 256 + threadIdx.x;
    int m = idx >> 16;
    int rem = idx & 65535;
    const float* W = (m == 0) ? Wk : (m == 1) ? Wq : Wv;
    g_w16[idx] = h16(W[rem]);
}

// ---------------------------------------------------------------------------
// projection: 512 threads (16 warps: mw 0..7 x nw 0..1), warp tile 16x96.
// pipelined, single-term fp16. buffers: {X 16K, W 24K} x2 = 80K
// ---------------------------------------------------------------------------
#define PB_X 0
#define PB_W 16384
#define PB_SZ 40960
#define P_TOT (2 * PB_SZ)           // 81920

__global__ void __launch_bounds__(512) proj_kernel(const float* __restrict__ x)
{
    extern __shared__ char smem[];
    const u32 sb = smem_u32(smem);
    const int tid = threadIdx.x;
    const int lane = tid & 31;
    const int wid = tid >> 5;
    const int mw = wid >> 1, nw = wid & 1;
    const int g = lane >> 2, tg = lane & 3;
    const int ln15 = lane & 15, l16 = lane >> 4;
    const int row0 = blockIdx.x * 128;

    float C[12][4];
#pragma unroll
    for (int j = 0; j < 12; j++)
#pragma unroll
        for (int r = 0; r < 4; r++) C[j][r] = 0.f;

    float4 xr[4];

    // prologue: LDG x[0], cp.async W[0]
#pragma unroll
    for (int i = 0; i < 4; i++) {
        int idx = tid + i * 512;
        int r = idx >> 4, q4 = idx & 15;
        xr[i] = *(const float4*)&x[(size_t)(row0 + r) * E_ + q4 * 4];
    }
#pragma unroll
    for (int i = 0; i < 3; i++) {
        int idx = tid + i * 512;              // < 1536
        int mat = idx >> 9;
        int rem = idx & 511;
        int r = rem >> 3, c8 = rem & 7;
        const u16* src = g_w16 + (size_t)mat * 65536 + r * 64 + c8 * 8;
        cpa16(sb + PB_W + mat * 8192 + swa(0, r, c8), src);
    }
    CP_COMMIT();

    for (int c = 0; c < 16; c++) {
        const u32 buf = sb + (c & 1) * PB_SZ;

        // convert prefetched x -> fp16 smem
#pragma unroll
        for (int i = 0; i < 4; i++) {
            int idx = tid + i * 512;
            int r = idx >> 4, q4 = idx & 15;
            u32 hA = cvt2h(xr[i].x, xr[i].y);
            u32 hB = cvt2h(xr[i].z, xr[i].w);
            u32 off = swa(0, r, q4 >> 1) + 8 * (q4 & 1);
            *(uint2*)(smem + (c & 1) * PB_SZ + PB_X + off) = make_uint2(hA, hB);
        }
        CP_WAIT0();
        __syncthreads();

        if (c < 15) {
            const int k1 = (c + 1) * 64;
#pragma unroll
            for (int i = 0; i < 4; i++) {
                int idx = tid + i * 512;
                int r = idx >> 4, q4 = idx & 15;
                xr[i] = *(const float4*)&x[(size_t)(row0 + r) * E_ + k1 + q4 * 4];
            }
            const u32 nb = ((c + 1) & 1) * PB_SZ;
#pragma unroll
            for (int i = 0; i < 3; i++) {
                int idx = tid + i * 512;
                int mat = idx >> 9;
                int rem = idx & 511;
                int r = rem >> 3, c8 = rem & 7;
                const u16* src = g_w16 + (size_t)mat * 65536 + (k1 + r) * 64 + c8 * 8;
                cpa16(sb + nb + PB_W + mat * 8192 + swa(0, r, c8), src);
            }
            CP_COMMIT();
        }

        // single-term MMA on buffer c&1
#pragma unroll
        for (int ks = 0; ks < 4; ks++) {
            u32 a0[4];
            ldsm4(a0[0], a0[1], a0[2], a0[3],
                  swa(buf + PB_X, 16 * mw + ln15, 2 * ks + l16));
#pragma unroll
            for (int gn = 0; gn < 6; gn++) {
                int n0 = nw * 96 + gn * 16;
                int mat = n0 >> 6, ln = n0 & 63;
                u32 b0, b1, b2, b3;
                ldsm4t(b0, b1, b2, b3,
                       swa(buf + PB_W + mat * 8192, 16 * ks + ln15, (ln >> 3) + l16));
                mma16816(C[2 * gn],     a0, b0, b1);
                mma16816(C[2 * gn + 1], a0, b2, b3);
            }
        }
    }

    // epilogue: single fp16 outputs (rows tok, tok+8)
    {
        int tok = row0 + 16 * mw + g;
        int bB = tok >> 11, tl = tok & 2047;
#pragma unroll
        for (int j = 0; j < 12; j++) {
            int col = nw * 96 + 8 * j + 2 * tg;
            int mat = col >> 6, h = col & 63;
            float v0 = C[j][0], v1 = C[j][1];
            float v2 = C[j][2], v3 = C[j][3];
            if (mat == 0) {                       // K -> [b][h][t] fp16
                size_t o0 = ((size_t)bB * 64 + h) * 2048 + tl;
                size_t o1 = ((size_t)bB * 64 + h + 1) * 2048 + tl;
                g_k16[o0]     = h16(v0); g_k16[o1]     = h16(v1);
                g_k16[o0 + 8] = h16(v2); g_k16[o1 + 8] = h16(v3);
            } else if (mat == 1) {                // Q scaled, fp16
                *(u32*)&g_q16[(size_t)tok * 64 + h] = cvt2h(v0 * 0.03125f, v1 * 0.03125f);
                *(u32*)&g_q16[(size_t)(tok + 8) * 64 + h] = cvt2h(v2 * 0.03125f, v3 * 0.03125f);
            } else {                              // V fp16
                *(u32*)&g_v16[(size_t)tok * 64 + h] = cvt2h(v0, v1);
                *(u32*)&g_v16[(size_t)(tok + 8) * 64 + h] = cvt2h(v2, v3);
            }
        }
    }
}

// ---------------------------------------------------------------------------
// attention: 512 threads (16 warps: mw 0..3 x nw 0..3), one q-tile per block.
// grid = 256 blocks, LARGEST-FIRST (qt = 31 - bid/8) for LPT scheduling.
// kv split 4 ways per tile; 2-round cross-nw reduction at the end.
// ---------------------------------------------------------------------------
#define A_Q    0
#define A_BUF  8192
#define A_BSZ  16384                // K 0, V 8192
#define A_REDA 8192                 // 64 x 68 fp32 = 17408
#define A_REDB 25600                // 64 x 68 fp32 = 17408 -> 43008
#define A_TOT  43008
// l partial scratch lives in the (dead) Q region during reduction:
#define A_LP2  0
#define A_LP3  256
#define A_LP1  512

__global__ void __launch_bounds__(512) attn_kernel(float* __restrict__ out)
{
    extern __shared__ char smem[];
    const u32 sb = smem_u32(smem);
    const int tid = threadIdx.x;
    const int lane = tid & 31;
    const int wid = tid >> 5;
    const int mw = wid & 3, nw = wid >> 2;
    const int g = lane >> 2, tg = lane & 3;
    const int ln15 = lane & 15, l16 = lane >> 4;
    const int bid = blockIdx.x;
    const int qt = 31 - (bid >> 3);           // largest workload first
    const int b  = bid & 7;
    const int q0 = qt * 64;
    const int nt = qt + 1;
    const float LOG2E = 1.4426950408889634f;

    const u16* Kg = g_k16 + (size_t)b * 64 * 2048;
    const u16* Vg = g_v16 + (size_t)b * 2048 * 64;

    // load Q (single fp16): 512 x 16B chunks
    {
        int r = tid >> 3, c8 = tid & 7;
        const u16* src = g_q16 + (size_t)(b * 2048 + q0 + r) * 64 + c8 * 8;
        uint4 v = *(const uint4*)src;
        *(uint4*)(smem + A_Q + swa(0, r, c8)) = v;
    }

    // prologue: async tile 0
#pragma unroll
    for (int i = 0; i < 2; i++) {
        int idx = tid + i * 512;
        int arr = idx >> 9;
        int rem = idx & 511;
        int r = rem >> 3, c8 = rem & 7;
        const u16* src;
        u32 dst = A_BUF;
        if (arr == 0) { src = Kg + (size_t)r * 2048 + c8 * 8; }
        else          { src = Vg + (size_t)r * 64 + c8 * 8; dst += 8192; }
        cpa16(sb + swa(dst, r, c8), src);
    }
    CP_COMMIT();

    float S[2][4], O[8][4];
    float l0 = 0.f, l1 = 0.f;
#pragma unroll
    for (int j = 0; j < 8; j++)
#pragma unroll
        for (int r = 0; r < 4; r++) O[j][r] = 0.f;

    u32 qf[4][4];
    bool qloaded = false;

    for (int t = 0; t < nt; t++) {
        CP_WAIT0();
        __syncthreads();

        // prefetch t+1 into the other slot (overlaps compute below)
        if (t + 1 < nt) {
            const int kv0 = (t + 1) * 64;
            const u32 bufn = A_BUF + ((t + 1) & 1) * A_BSZ;
#pragma unroll
            for (int i = 0; i < 2; i++) {
                int idx = tid + i * 512;
                int arr = idx >> 9;
                int rem = idx & 511;
                int r = rem >> 3, c8 = rem & 7;
                const u16* src;
                u32 dst = bufn;
                if (arr == 0) { src = Kg + (size_t)r * 2048 + kv0 + c8 * 8; }
                else          { src = Vg + (size_t)(kv0 + r) * 64 + c8 * 8; dst += 8192; }
                cpa16(sb + swa(dst, r, c8), src);
            }
            CP_COMMIT();
        }

        if (!qloaded) {
            qloaded = true;
#pragma unroll
            for (int ks = 0; ks < 4; ks++)
                ldsm4(qf[ks][0], qf[ks][1], qf[ks][2], qf[ks][3],
                      swa(sb + A_Q, 16 * mw + ln15, 2 * ks + l16));
        }

        const u32 buf = sb + A_BUF + (t & 1) * A_BSZ;
        const u32 KT = buf, VT = buf + 8192;

        // S slice 16x16: kv cols nw*16..+15
#pragma unroll
        for (int j = 0; j < 2; j++)
#pragma unroll
            for (int r = 0; r < 4; r++) S[j][r] = 0.f;
#pragma unroll
        for (int ks = 0; ks < 4; ks++) {
            u32 b0, b1, b2, b3;
            ldsm4t(b0, b1, b2, b3,
                   swa(KT, 16 * ks + ln15, 2 * nw + l16));
            mma16816(S[0], qf[ks], b0, b1);
            mma16816(S[1], qf[ks], b2, b3);
        }

        // exp + mask + l partials
        const bool diag = (t == nt - 1);
        const int rl0 = 16 * mw + g;
#pragma unroll
        for (int j = 0; j < 2; j++) {
            int col0 = nw * 16 + 8 * j + 2 * tg;
            float p0 = fast_exp2(S[j][0] * LOG2E);
            float p1 = fast_exp2(S[j][1] * LOG2E);
            float p2 = fast_exp2(S[j][2] * LOG2E);
            float p3 = fast_exp2(S[j][3] * LOG2E);
            if (diag) {
                if (col0 > rl0)         p0 = 0.f;
                if (col0 + 1 > rl0)     p1 = 0.f;
                if (col0 > rl0 + 8)     p2 = 0.f;
                if (col0 + 1 > rl0 + 8) p3 = 0.f;
            }
            l0 += p0 + p1;
            l1 += p2 + p3;
            S[j][0] = p0; S[j][1] = p1; S[j][2] = p2; S[j][3] = p3;
        }

        // P fp16 A-fragment (m16 k16, k = warp's 16 kv)
        u32 ph[4];
        ph[0] = cvt2h(S[0][0], S[0][1]);
        ph[1] = cvt2h(S[0][2], S[0][3]);
        ph[2] = cvt2h(S[1][0], S[1][1]);
        ph[3] = cvt2h(S[1][2], S[1][3]);

        // O += P @ V over warp's 16 kv rows
        {
            int vr = nw * 16 + ln15;
#pragma unroll
            for (int gh = 0; gh < 4; gh++) {
                u32 b0, b1, b2, b3;
                ldsm4t(b0, b1, b2, b3, swa(VT, vr, 2 * gh + l16));
                mma16816(O[2 * gh],     ph, b0, b1);
                mma16816(O[2 * gh + 1], ph, b2, b3);
            }
        }
    }

    __syncthreads();                  // all compute done before scratch reuse

    // reduce l over the 4 tg lanes sharing each row
    l0 += __shfl_xor_sync(0xffffffffu, l0, 1);
    l0 += __shfl_xor_sync(0xffffffffu, l0, 2);
    l1 += __shfl_xor_sync(0xffffffffu, l1, 1);
    l1 += __shfl_xor_sync(0xffffffffu, l1, 2);

    float* REDA = (float*)(smem + A_REDA);
    float* REDB = (float*)(smem + A_REDB);
    float* LP2  = (float*)(smem + A_LP2);
    float* LP3  = (float*)(smem + A_LP3);
    float* LP1  = (float*)(smem + A_LP1);
    const int r0 = 16 * mw + g;

    // round 1: nw 2,3 publish
    if (nw == 2 || nw == 3) {
        float* RED = (nw == 2) ? REDA : REDB;
#pragma unroll
        for (int j = 0; j < 8; j++) {
            int col = 8 * j + 2 * tg;
            RED[r0 * 68 + col]           = O[j][0];
            RED[r0 * 68 + col + 1]       = O[j][1];
            RED[(r0 + 8) * 68 + col]     = O[j][2];
            RED[(r0 + 8) * 68 + col + 1] = O[j][3];
        }
        if (tg == 0) {
            float* LP = (nw == 2) ? LP2 : LP3;
            LP[r0] = l0; LP[r0 + 8] = l1;
        }
    }
    __syncthreads();
    if (nw == 0 || nw == 1) {
        float* RED = (nw == 0) ? REDA : REDB;
        float* LP  = (nw == 0) ? LP2 : LP3;
#pragma unroll
        for (int j = 0; j < 8; j++) {
            int col = 8 * j + 2 * tg;
            O[j][0] += RED[r0 * 68 + col];
            O[j][1] += RED[r0 * 68 + col + 1];
            O[j][2] += RED[(r0 + 8) * 68 + col];
            O[j][3] += RED[(r0 + 8) * 68 + col + 1];
        }
        l0 += LP[r0]; l1 += LP[r0 + 8];
    }
    __syncthreads();
    // round 2: nw 1 publishes its combined partial
    if (nw == 1) {
#pragma unroll
        for (int j = 0; j < 8; j++) {
            int col = 8 * j + 2 * tg;
            REDA[r0 * 68 + col]           = O[j][0];
            REDA[r0 * 68 + col + 1]       = O[j][1];
            REDA[(r0 + 8) * 68 + col]     = O[j][2];
            REDA[(r0 + 8) * 68 + col + 1] = O[j][3];
        }
        if (tg == 0) { LP1[r0] = l0; LP1[r0 + 8] = l1; }
    }
    __syncthreads();
    if (nw == 0) {
        float inv0 = 1.f / (l0 + LP1[r0]);
        float inv1 = 1.f / (l1 + LP1[r0 + 8]);
        float* O0 = out + ((size_t)b * T_ + q0 + r0) * H_;
        float* O1 = O0 + 8 * H_;
#pragma unroll
        for (int j = 0; j < 8; j++) {
            int col = 8 * j + 2 * tg;
            *(float2*)&O0[col] = make_float2(
                (O[j][0] + REDA[r0 * 68 + col]) * inv0,
                (O[j][1] + REDA[r0 * 68 + col + 1]) * inv0);
            *(float2*)&O1[col] = make_float2(
                (O[j][2] + REDA[(r0 + 8) * 68 + col]) * inv1,
                (O[j][3] + REDA[(r0 + 8) * 68 + col + 1]) * inv1);
        }
    }
}

// ---------------------------------------------------------------------------
extern "C" void kernel_launch(void* const* d_in, const int* in_sizes, int n_in,
                              void* d_out, int out_size)
{
    const float* x  = (const float*)d_in[0];
    const float* Wk = (const float*)d_in[1];
    const float* Wq = (const float*)d_in[2];
    const float* Wv = (const float*)d_in[3];
    float* out = (float*)d_out;
    (void)in_sizes; (void)n_in; (void)out_size;

    cudaFuncSetAttribute(proj_kernel,
                         cudaFuncAttributeMaxDynamicSharedMemorySize, P_TOT);
    cudaFuncSetAttribute(attn_kernel,
                         cudaFuncAttributeMaxDynamicSharedMemorySize, A_TOT);

    prep_w_kernel<<<768, 256>>>(Wk, Wq, Wv);
    proj_kernel<<<BT_ / 128, 512, P_TOT>>>(x);
    attn_kernel<<<256, 512, A_TOT>>>(out);
}

// round 10
// speedup vs baseline: 1.0792x; 1.0792x over previous
#include <cuda_runtime.h>
#include <cstdint>

#define B_  8
#define T_  2048
#define E_  1024
#define H_  64
#define BT_ (B_ * T_)

typedef unsigned int u32;
typedef unsigned short u16;

// fp16 scratch (static device arrays; no runtime alloc)
__device__ u16 g_w16[3 * E_ * H_];   // W fp16 [m][e][n]
__device__ u16 g_q16[BT_ * H_];      // [t][h] (scaled log2e/32)
__device__ u16 g_k16[BT_ * H_];      // [b][h][t] (transposed)
__device__ u16 g_v16[BT_ * H_];      // [t][h]

// ---------------------------------------------------------------------------
__device__ __forceinline__ u32 smem_u32(const void* p) {
    u32 a;
    asm("{ .reg .u64 t; cvta.to.shared.u64 t, %1; cvt.u32.u64 %0, t; }"
        : "=r"(a) : "l"(p));
    return a;
}
__device__ __forceinline__ u32 swa(u32 base, int r, int c) {
    return base + r * 128 + (((c ^ (r & 7)) & 7) << 4);
}
__device__ __forceinline__ u32 cvt2h(float a, float b) {
    u32 r;
    asm("cvt.rn.f16x2.f32 %0, %1, %2;" : "=r"(r) : "f"(b), "f"(a));
    return r;
}
__device__ __forceinline__ u16 h16(float a) {
    u16 r;
    asm("cvt.rn.f16.f32 %0, %1;" : "=h"(r) : "f"(a));
    return r;
}
__device__ __forceinline__ u32 ex2h2(u32 s) {
    u32 d;
    asm("ex2.approx.f16x2 %0, %1;" : "=r"(d) : "r"(s));
    return d;
}
__device__ __forceinline__ float hsum2(u32 p) {
    float f;
    asm("{ .reg .b16 lo,hi; .reg .f32 a,b;\n\t"
        "mov.b32 {lo,hi}, %1; cvt.f32.f16 a, lo; cvt.f32.f16 b, hi;\n\t"
        "add.f32 %0, a, b; }" : "=f"(f) : "r"(p));
    return f;
}
__device__ __forceinline__ void ldsm4(u32& r0, u32& r1, u32& r2, u32& r3, u32 a) {
    asm volatile("ldmatrix.sync.aligned.m8n8.x4.shared.b16 {%0,%1,%2,%3}, [%4];"
                 : "=r"(r0), "=r"(r1), "=r"(r2), "=r"(r3) : "r"(a));
}
__device__ __forceinline__ void ldsm4t(u32& r0, u32& r1, u32& r2, u32& r3, u32 a) {
    asm volatile("ldmatrix.sync.aligned.m8n8.x4.trans.shared.b16 {%0,%1,%2,%3}, [%4];"
                 : "=r"(r0), "=r"(r1), "=r"(r2), "=r"(r3) : "r"(a));
}
__device__ __forceinline__ void mma16816(float* c, const u32* a, u32 b0, u32 b1) {
    asm volatile(
        "mma.sync.aligned.m16n8k16.row.col.f32.f16.f16.f32 "
        "{%0,%1,%2,%3}, {%4,%5,%6,%7}, {%8,%9}, {%0,%1,%2,%3};"
        : "+f"(c[0]), "+f"(c[1]), "+f"(c[2]), "+f"(c[3])
        : "r"(a[0]), "r"(a[1]), "r"(a[2]), "r"(a[3]), "r"(b0), "r"(b1));
}
__device__ __forceinline__ void cpa16(u32 s, const void* g) {
    asm volatile("cp.async.cg.shared.global [%0], [%1], 16;" :: "r"(s), "l"(g));
}
#define CP_COMMIT() asm volatile("cp.async.commit_group;" ::: "memory")
#define CP_WAIT0()  asm volatile("cp.async.wait_group 0;" ::: "memory")

// ---------------------------------------------------------------------------
__global__ void __launch_bounds__(256) prep_w_kernel(
    const float* __restrict__ Wk, const float* __restrict__ Wq,
    const float* __restrict__ Wv)
{
    int idx = blockIdx.x * 256 + threadIdx.x;
    int m = idx >> 16;
    int rem = idx & 65535;
    const float* W = (m == 0) ? Wk : (m == 1) ? Wq : Wv;
    g_w16[idx] = h16(W[rem]);
}

// ---------------------------------------------------------------------------
// projection: 64 rows/block, 256 threads (8 warps: mw 0..3 x nw 0..1),
// grid 256 -> 2 blocks/SM. pipelined. buffers {X 8K, W 24K} x2 = 64K
// ---------------------------------------------------------------------------
#define PB_X 0
#define PB_W 8192
#define PB_SZ 32768
#define P_TOT (2 * PB_SZ)           // 65536

__global__ void __launch_bounds__(256, 2) proj_kernel(const float* __restrict__ x)
{
    extern __shared__ char smem[];
    const u32 sb = smem_u32(smem);
    const int tid = threadIdx.x;
    const int lane = tid & 31;
    const int wid = tid >> 5;
    const int mw = wid >> 1, nw = wid & 1;
    const int g = lane >> 2, tg = lane & 3;
    const int ln15 = lane & 15, l16 = lane >> 4;
    const int row0 = blockIdx.x * 64;

    float C[12][4];
#pragma unroll
    for (int j = 0; j < 12; j++)
#pragma unroll
        for (int r = 0; r < 4; r++) C[j][r] = 0.f;

    float4 xr[4];

    // prologue: LDG x[0], cp.async W[0]
#pragma unroll
    for (int i = 0; i < 4; i++) {
        int idx = tid + i * 256;              // < 1024
        int r = idx >> 4, q4 = idx & 15;
        xr[i] = *(const float4*)&x[(size_t)(row0 + r) * E_ + q4 * 4];
    }
#pragma unroll
    for (int i = 0; i < 6; i++) {
        int idx = tid + i * 256;              // < 1536
        int mat = idx >> 9;
        int rem = idx & 511;
        int r = rem >> 3, c8 = rem & 7;
        const u16* src = g_w16 + (size_t)mat * 65536 + r * 64 + c8 * 8;
        cpa16(sb + PB_W + mat * 8192 + swa(0, r, c8), src);
    }
    CP_COMMIT();

    for (int c = 0; c < 16; c++) {
        const u32 buf = sb + (c & 1) * PB_SZ;

        // convert prefetched x -> fp16 smem
#pragma unroll
        for (int i = 0; i < 4; i++) {
            int idx = tid + i * 256;
            int r = idx >> 4, q4 = idx & 15;
            u32 hA = cvt2h(xr[i].x, xr[i].y);
            u32 hB = cvt2h(xr[i].z, xr[i].w);
            u32 off = swa(0, r, q4 >> 1) + 8 * (q4 & 1);
            *(uint2*)(smem + (c & 1) * PB_SZ + PB_X + off) = make_uint2(hA, hB);
        }
        CP_WAIT0();
        __syncthreads();

        if (c < 15) {
            const int k1 = (c + 1) * 64;
#pragma unroll
            for (int i = 0; i < 4; i++) {
                int idx = tid + i * 256;
                int r = idx >> 4, q4 = idx & 15;
                xr[i] = *(const float4*)&x[(size_t)(row0 + r) * E_ + k1 + q4 * 4];
            }
            const u32 nb = ((c + 1) & 1) * PB_SZ;
#pragma unroll
            for (int i = 0; i < 6; i++) {
                int idx = tid + i * 256;
                int mat = idx >> 9;
                int rem = idx & 511;
                int r = rem >> 3, c8 = rem & 7;
                const u16* src = g_w16 + (size_t)mat * 65536 + (k1 + r) * 64 + c8 * 8;
                cpa16(sb + nb + PB_W + mat * 8192 + swa(0, r, c8), src);
            }
            CP_COMMIT();
        }

        // single-term MMA on buffer c&1
#pragma unroll
        for (int ks = 0; ks < 4; ks++) {
            u32 a0[4];
            ldsm4(a0[0], a0[1], a0[2], a0[3],
                  swa(buf + PB_X, 16 * mw + ln15, 2 * ks + l16));
#pragma unroll
            for (int gn = 0; gn < 6; gn++) {
                int n0 = nw * 96 + gn * 16;
                int mat = n0 >> 6, ln = n0 & 63;
                u32 b0, b1, b2, b3;
                ldsm4t(b0, b1, b2, b3,
                       swa(buf + PB_W + mat * 8192, 16 * ks + ln15, (ln >> 3) + l16));
                mma16816(C[2 * gn],     a0, b0, b1);
                mma16816(C[2 * gn + 1], a0, b2, b3);
            }
        }
    }

    // epilogue: fp16 outputs (rows tok, tok+8); Q pre-scaled by log2e/32
    {
        const float QSC = 0.045084219770295f;   // 2^-5 * log2(e)
        int tok = row0 + 16 * mw + g;
        int bB = tok >> 11, tl = tok & 2047;
#pragma unroll
        for (int j = 0; j < 12; j++) {
            int col = nw * 96 + 8 * j + 2 * tg;
            int mat = col >> 6, h = col & 63;
            float v0 = C[j][0], v1 = C[j][1];
            float v2 = C[j][2], v3 = C[j][3];
            if (mat == 0) {                       // K -> [b][h][t] fp16
                size_t o0 = ((size_t)bB * 64 + h) * 2048 + tl;
                size_t o1 = ((size_t)bB * 64 + h + 1) * 2048 + tl;
                g_k16[o0]     = h16(v0); g_k16[o1]     = h16(v1);
                g_k16[o0 + 8] = h16(v2); g_k16[o1 + 8] = h16(v3);
            } else if (mat == 1) {                // Q scaled
                *(u32*)&g_q16[(size_t)tok * 64 + h] = cvt2h(v0 * QSC, v1 * QSC);
                *(u32*)&g_q16[(size_t)(tok + 8) * 64 + h] = cvt2h(v2 * QSC, v3 * QSC);
            } else {                              // V fp16
                *(u32*)&g_v16[(size_t)tok * 64 + h] = cvt2h(v0, v1);
                *(u32*)&g_v16[(size_t)(tok + 8) * 64 + h] = cvt2h(v2, v3);
            }
        }
    }
}

// ---------------------------------------------------------------------------
// attention: 256 threads, 8 warps (mw 0..3 x nw 0..1), one q-tile per block.
// grid 256, 2 blocks/SM co-resident; big+small interleave so each SM's pair
// sums ~33 tiles. exp via ex2.approx.f16x2 (Q carries log2e).
// ---------------------------------------------------------------------------
#define A_Q   0
#define A_BUF 8192
#define A_BSZ 16384                 // K 0, V 8192
#define A_TOT (A_BUF + 2 * A_BSZ)   // 40960
#define A_RED A_BUF
#define A_LRED (A_BUF + 64 * 68 * 4)

__global__ void __launch_bounds__(256, 2) attn_kernel(float* __restrict__ out)
{
    extern __shared__ char smem[];
    const u32 sb = smem_u32(smem);
    const int tid = threadIdx.x;
    const int lane = tid & 31;
    const int wid = tid >> 5;
    const int mw = wid & 3, nw = wid >> 2;
    const int g = lane >> 2, tg = lane & 3;
    const int ln15 = lane & 15, l16 = lane >> 4;
    const int bid = blockIdx.x;
    // big+small interleave: resident pair (bid, bid+148) sums ~33 tiles
    const int qt = (bid < 128) ? (31 - (bid >> 3)) : ((bid - 128) >> 3);
    const int b  = bid & 7;
    const int q0 = qt * 64;
    const int nt = qt + 1;

    const u16* Kg = g_k16 + (size_t)b * 64 * 2048;
    const u16* Vg = g_v16 + (size_t)b * 2048 * 64;

    // load Q (fp16, log2e-folded): 512 chunks
#pragma unroll
    for (int i = 0; i < 2; i++) {
        int idx = tid + i * 256;
        int r = idx >> 3, c8 = idx & 7;
        const u16* src = g_q16 + (size_t)(b * 2048 + q0 + r) * 64 + c8 * 8;
        uint4 v = *(const uint4*)src;
        *(uint4*)(smem + A_Q + swa(0, r, c8)) = v;
    }

    // prologue: async tile 0
#pragma unroll
    for (int i = 0; i < 4; i++) {
        int idx = tid + i * 256;
        int arr = idx >> 9;
        int rem = idx & 511;
        int r = rem >> 3, c8 = rem & 7;
        const u16* src;
        u32 dst = A_BUF;
        if (arr == 0) { src = Kg + (size_t)r * 2048 + c8 * 8; }
        else          { src = Vg + (size_t)r * 64 + c8 * 8; dst += 8192; }
        cpa16(sb + swa(dst, r, c8), src);
    }
    CP_COMMIT();

    float S[4][4], O[8][4];
    float l0 = 0.f, l1 = 0.f;
#pragma unroll
    for (int j = 0; j < 8; j++)
#pragma unroll
        for (int r = 0; r < 4; r++) O[j][r] = 0.f;

    u32 qf[4][4];
    bool qloaded = false;

    for (int t = 0; t < nt; t++) {
        CP_WAIT0();
        __syncthreads();

        // prefetch t+1 into the other slot (overlaps compute below)
        if (t + 1 < nt) {
            const int kv0 = (t + 1) * 64;
            const u32 bufn = A_BUF + ((t + 1) & 1) * A_BSZ;
#pragma unroll
            for (int i = 0; i < 4; i++) {
                int idx = tid + i * 256;
                int arr = idx >> 9;
                int rem = idx & 511;
                int r = rem >> 3, c8 = rem & 7;
                const u16* src;
                u32 dst = bufn;
                if (arr == 0) { src = Kg + (size_t)r * 2048 + kv0 + c8 * 8; }
                else          { src = Vg + (size_t)(kv0 + r) * 64 + c8 * 8; dst += 8192; }
                cpa16(sb + swa(dst, r, c8), src);
            }
            CP_COMMIT();
        }

        if (!qloaded) {
            qloaded = true;
#pragma unroll
            for (int ks = 0; ks < 4; ks++)
                ldsm4(qf[ks][0], qf[ks][1], qf[ks][2], qf[ks][3],
                      swa(sb + A_Q, 16 * mw + ln15, 2 * ks + l16));
        }

        const u32 buf = sb + A_BUF + (t & 1) * A_BSZ;
        const u32 KT = buf, VT = buf + 8192;

        // S slice 16x32 (kv cols nw*32..+31)
#pragma unroll
        for (int j = 0; j < 4; j++)
#pragma unroll
            for (int r = 0; r < 4; r++) S[j][r] = 0.f;
#pragma unroll
        for (int ks = 0; ks < 4; ks++) {
#pragma unroll
            for (int p = 0; p < 2; p++) {
                u32 b0, b1, b2, b3;
                ldsm4t(b0, b1, b2, b3,
                       swa(KT, 16 * ks + ln15, nw * 4 + 2 * p + l16));
                mma16816(S[2 * p],     qf[ks], b0, b1);
                mma16816(S[2 * p + 1], qf[ks], b2, b3);
            }
        }

        // p = 2^s via f16x2; mask; accumulate l; build P fragments directly
        const bool diag = (t == nt - 1);
        const int rl0 = 16 * mw + g;
        u32 ph[2][4];
#pragma unroll
        for (int j = 0; j < 4; j++) {
            int col0 = nw * 32 + 8 * j + 2 * tg;
            u32 p0 = ex2h2(cvt2h(S[j][0], S[j][1]));   // row rl0
            u32 p1 = ex2h2(cvt2h(S[j][2], S[j][3]));   // row rl0+8
            if (diag) {
                u32 m0 = (col0 <= rl0 ? 0xFFFFu : 0u) | (col0 + 1 <= rl0 ? 0xFFFF0000u : 0u);
                u32 m1 = (col0 <= rl0 + 8 ? 0xFFFFu : 0u) | (col0 + 1 <= rl0 + 8 ? 0xFFFF0000u : 0u);
                p0 &= m0;
                p1 &= m1;
            }
            l0 += hsum2(p0);
            l1 += hsum2(p1);
            ph[j >> 1][(j & 1) * 2]     = p0;
            ph[j >> 1][(j & 1) * 2 + 1] = p1;
        }

        // O += P @ V over warp's 32 kv rows
#pragma unroll
        for (int ks = 0; ks < 2; ks++) {
            int vr = nw * 32 + 16 * ks + ln15;
#pragma unroll
            for (int gh = 0; gh < 4; gh++) {
                u32 b0, b1, b2, b3;
                ldsm4t(b0, b1, b2, b3, swa(VT, vr, 2 * gh + l16));
                mma16816(O[2 * gh],     ph[ks], b0, b1);
                mma16816(O[2 * gh + 1], ph[ks], b2, b3);
            }
        }
    }

    __syncthreads();                  // compute done before scratch reuse

    // reduce l across 4 lanes sharing a row
    l0 += __shfl_xor_sync(0xffffffffu, l0, 1);
    l0 += __shfl_xor_sync(0xffffffffu, l0, 2);
    l1 += __shfl_xor_sync(0xffffffffu, l1, 1);
    l1 += __shfl_xor_sync(0xffffffffu, l1, 2);

    // cross-nw reduction via smem (aliases KV buffers)
    float* RED  = (float*)(smem + A_RED);
    float* LRED = (float*)(smem + A_LRED);
    const int r0 = 16 * mw + g;
    if (nw == 1) {
#pragma unroll
        for (int j = 0; j < 8; j++) {
            int col = 8 * j + 2 * tg;
            RED[r0 * 68 + col]           = O[j][0];
            RED[r0 * 68 + col + 1]       = O[j][1];
            RED[(r0 + 8) * 68 + col]     = O[j][2];
            RED[(r0 + 8) * 68 + col + 1] = O[j][3];
        }
        if (tg == 0) { LRED[r0] = l0; LRED[r0 + 8] = l1; }
    }
    __syncthreads();
    if (nw == 0) {
        float inv0 = 1.f / (l0 + LRED[r0]);
        float inv1 = 1.f / (l1 + LRED[r0 + 8]);
        float* O0 = out + ((size_t)b * T_ + q0 + r0) * H_;
        float* O1 = O0 + 8 * H_;
#pragma unroll
        for (int j = 0; j < 8; j++) {
            int col = 8 * j + 2 * tg;
            *(float2*)&O0[col] = make_float2(
                (O[j][0] + RED[r0 * 68 + col]) * inv0,
                (O[j][1] + RED[r0 * 68 + col + 1]) * inv0);
            *(float2*)&O1[col] = make_float2(
                (O[j][2] + RED[(r0 + 8) * 68 + col]) * inv1,
                (O[j][3] + RED[(r0 + 8) * 68 + col + 1]) * inv1);
        }
    }
}

// ---------------------------------------------------------------------------
extern "C" void kernel_launch(void* const* d_in, const int* in_sizes, int n_in,
                              void* d_out, int out_size)
{
    const float* x  = (const float*)d_in[0];
    const float* Wk = (const float*)d_in[1];
    const float* Wq = (const float*)d_in[2];
    const float* Wv = (const float*)d_in[3];
    float* out = (float*)d_out;
    (void)in_sizes; (void)n_in; (void)out_size;

    cudaFuncSetAttribute(proj_kernel,
                         cudaFuncAttributeMaxDynamicSharedMemorySize, P_TOT);
    cudaFuncSetAttribute(attn_kernel,
                         cudaFuncAttributeMaxDynamicSharedMemorySize, A_TOT);

    prep_w_kernel<<<768, 256>>>(Wk, Wq, Wv);
    proj_kernel<<<BT_ / 64, 256, P_TOT>>>(x);
    attn_kernel<<<256, 256, A_TOT>>>(out);
}

// round 11
// speedup vs baseline: 1.1728x; 1.0868x over previous
#include <cuda_runtime.h>
#include <cstdint>

#define B_  8
#define T_  2048
#define E_  1024
#define H_  64
#define BT_ (B_ * T_)

typedef unsigned int u32;
typedef unsigned short u16;

// fp16 scratch (static device arrays; no runtime alloc)
__device__ u16 g_w16[3 * E_ * H_];   // W fp16 [m][e][n]
__device__ u16 g_q16[BT_ * H_];      // [t][h] (scaled log2e/32)
__device__ u16 g_k16[BT_ * H_];      // [b][h][t] (transposed)
__device__ u16 g_v16[BT_ * H_];      // [t][h]

// ---------------------------------------------------------------------------
__device__ __forceinline__ u32 smem_u32(const void* p) {
    u32 a;
    asm("{ .reg .u64 t; cvta.to.shared.u64 t, %1; cvt.u32.u64 %0, t; }"
        : "=r"(a) : "l"(p));
    return a;
}
__device__ __forceinline__ u32 swa(u32 base, int r, int c) {
    return base + r * 128 + (((c ^ (r & 7)) & 7) << 4);
}
__device__ __forceinline__ u32 cvt2h(float a, float b) {
    u32 r;
    asm("cvt.rn.f16x2.f32 %0, %1, %2;" : "=r"(r) : "f"(b), "f"(a));
    return r;
}
__device__ __forceinline__ u16 h16(float a) {
    u16 r;
    asm("cvt.rn.f16.f32 %0, %1;" : "=h"(r) : "f"(a));
    return r;
}
__device__ __forceinline__ u32 ex2h2(u32 s) {
    u32 d;
    asm("ex2.approx.f16x2 %0, %1;" : "=r"(d) : "r"(s));
    return d;
}
__device__ __forceinline__ float hsum2(u32 p) {
    float f;
    asm("{ .reg .b16 lo,hi; .reg .f32 a,b;\n\t"
        "mov.b32 {lo,hi}, %1; cvt.f32.f16 a, lo; cvt.f32.f16 b, hi;\n\t"
        "add.f32 %0, a, b; }" : "=f"(f) : "r"(p));
    return f;
}
__device__ __forceinline__ void ldsm4(u32& r0, u32& r1, u32& r2, u32& r3, u32 a) {
    asm volatile("ldmatrix.sync.aligned.m8n8.x4.shared.b16 {%0,%1,%2,%3}, [%4];"
                 : "=r"(r0), "=r"(r1), "=r"(r2), "=r"(r3) : "r"(a));
}
__device__ __forceinline__ void ldsm4t(u32& r0, u32& r1, u32& r2, u32& r3, u32 a) {
    asm volatile("ldmatrix.sync.aligned.m8n8.x4.trans.shared.b16 {%0,%1,%2,%3}, [%4];"
                 : "=r"(r0), "=r"(r1), "=r"(r2), "=r"(r3) : "r"(a));
}
__device__ __forceinline__ void mma16816(float* c, const u32* a, u32 b0, u32 b1) {
    asm volatile(
        "mma.sync.aligned.m16n8k16.row.col.f32.f16.f16.f32 "
        "{%0,%1,%2,%3}, {%4,%5,%6,%7}, {%8,%9}, {%0,%1,%2,%3};"
        : "+f"(c[0]), "+f"(c[1]), "+f"(c[2]), "+f"(c[3])
        : "r"(a[0]), "r"(a[1]), "r"(a[2]), "r"(a[3]), "r"(b0), "r"(b1));
}
__device__ __forceinline__ void cpa16(u32 s, const void* g) {
    asm volatile("cp.async.cg.shared.global [%0], [%1], 16;" :: "r"(s), "l"(g));
}
#define CP_COMMIT() asm volatile("cp.async.commit_group;" ::: "memory")
#define CP_WAIT0()  asm volatile("cp.async.wait_group 0;" ::: "memory")

// ---------------------------------------------------------------------------
// prep: vectorized fp32 -> fp16 W convert (float4 in, uint2 out)
// ---------------------------------------------------------------------------
__global__ void __launch_bounds__(256) prep_w_kernel(
    const float* __restrict__ Wk, const float* __restrict__ Wq,
    const float* __restrict__ Wv)
{
    int q = blockIdx.x * 256 + threadIdx.x;        // < 49152 quads
    int idx = q * 4;
    int m = idx >> 16;
    int rem = idx & 65535;
    const float* W = (m == 0) ? Wk : (m == 1) ? Wq : Wv;
    float4 v = *(const float4*)&W[rem];
    *(uint2*)&g_w16[idx] = make_uint2(cvt2h(v.x, v.y), cvt2h(v.z, v.w));
}

// ---------------------------------------------------------------------------
// projection: 64 rows/block, 256 threads (8 warps: mw 0..1 x nw 0..3),
// warp tile 32x48 (crossbar-optimal). 2 blocks/SM. buffers {X 8K, W 24K} x2.
// ---------------------------------------------------------------------------
#define PB_X 0
#define PB_W 8192
#define PB_SZ 32768
#define P_TOT (2 * PB_SZ)           // 65536

__global__ void __launch_bounds__(256, 2) proj_kernel(const float* __restrict__ x)
{
    extern __shared__ char smem[];
    const u32 sb = smem_u32(smem);
    const int tid = threadIdx.x;
    const int lane = tid & 31;
    const int wid = tid >> 5;
    const int mw = wid >> 2, nw = wid & 3;        // 2 x 4
    const int g = lane >> 2, tg = lane & 3;
    const int ln15 = lane & 15, l16 = lane >> 4;
    const int row0 = blockIdx.x * 64;

    float C[2][6][4];
#pragma unroll
    for (int mt = 0; mt < 2; mt++)
#pragma unroll
        for (int j = 0; j < 6; j++)
#pragma unroll
            for (int r = 0; r < 4; r++) C[mt][j][r] = 0.f;

    float4 xr[4];

    // prologue: LDG x[0], cp.async W[0]
#pragma unroll
    for (int i = 0; i < 4; i++) {
        int idx = tid + i * 256;              // < 1024
        int r = idx >> 4, q4 = idx & 15;
        xr[i] = *(const float4*)&x[(size_t)(row0 + r) * E_ + q4 * 4];
    }
#pragma unroll
    for (int i = 0; i < 6; i++) {
        int idx = tid + i * 256;              // < 1536
        int mat = idx >> 9;
        int rem = idx & 511;
        int r = rem >> 3, c8 = rem & 7;
        const u16* src = g_w16 + (size_t)mat * 65536 + r * 64 + c8 * 8;
        cpa16(sb + PB_W + mat * 8192 + swa(0, r, c8), src);
    }
    CP_COMMIT();

    for (int c = 0; c < 16; c++) {
        const u32 buf = sb + (c & 1) * PB_SZ;

        // convert prefetched x -> fp16 smem
#pragma unroll
        for (int i = 0; i < 4; i++) {
            int idx = tid + i * 256;
            int r = idx >> 4, q4 = idx & 15;
            u32 hA = cvt2h(xr[i].x, xr[i].y);
            u32 hB = cvt2h(xr[i].z, xr[i].w);
            u32 off = swa(0, r, q4 >> 1) + 8 * (q4 & 1);
            *(uint2*)(smem + (c & 1) * PB_SZ + PB_X + off) = make_uint2(hA, hB);
        }
        CP_WAIT0();
        __syncthreads();

        if (c < 15) {
            const int k1 = (c + 1) * 64;
#pragma unroll
            for (int i = 0; i < 4; i++) {
                int idx = tid + i * 256;
                int r = idx >> 4, q4 = idx & 15;
                xr[i] = *(const float4*)&x[(size_t)(row0 + r) * E_ + k1 + q4 * 4];
            }
            const u32 nb = ((c + 1) & 1) * PB_SZ;
#pragma unroll
            for (int i = 0; i < 6; i++) {
                int idx = tid + i * 256;
                int mat = idx >> 9;
                int rem = idx & 511;
                int r = rem >> 3, c8 = rem & 7;
                const u16* src = g_w16 + (size_t)mat * 65536 + (k1 + r) * 64 + c8 * 8;
                cpa16(sb + nb + PB_W + mat * 8192 + swa(0, r, c8), src);
            }
            CP_COMMIT();
        }

        // MMA: warp rows 32*mw..+31, cols nw*48..+47
#pragma unroll
        for (int ks = 0; ks < 4; ks++) {
            u32 a0[4], a1[4];
            ldsm4(a0[0], a0[1], a0[2], a0[3],
                  swa(buf + PB_X, 32 * mw + ln15, 2 * ks + l16));
            ldsm4(a1[0], a1[1], a1[2], a1[3],
                  swa(buf + PB_X, 32 * mw + 16 + ln15, 2 * ks + l16));
#pragma unroll
            for (int gi = 0; gi < 3; gi++) {
                int colg = nw * 48 + gi * 16;
                int mat = colg >> 6, ln = colg & 63;
                u32 b0, b1, b2, b3;
                ldsm4t(b0, b1, b2, b3,
                       swa(buf + PB_W + mat * 8192, 16 * ks + ln15, (ln >> 3) + l16));
                mma16816(C[0][2 * gi],     a0, b0, b1);
                mma16816(C[0][2 * gi + 1], a0, b2, b3);
                mma16816(C[1][2 * gi],     a1, b0, b1);
                mma16816(C[1][2 * gi + 1], a1, b2, b3);
            }
        }
    }

    // epilogue: fp16 outputs; Q pre-scaled by log2e/32
    {
        const float QSC = 0.045084219770295f;   // 2^-5 * log2(e)
#pragma unroll
        for (int mt = 0; mt < 2; mt++) {
            int tok = row0 + 32 * mw + 16 * mt + g;
            int bB = tok >> 11, tl = tok & 2047;
#pragma unroll
            for (int j = 0; j < 6; j++) {
                int colg = nw * 48 + j * 8 + 2 * tg;
                int mat = colg >> 6, h = colg & 63;
                float v0 = C[mt][j][0], v1 = C[mt][j][1];
                float v2 = C[mt][j][2], v3 = C[mt][j][3];
                if (mat == 0) {                   // K -> [b][h][t] fp16
                    size_t o0 = ((size_t)bB * 64 + h) * 2048 + tl;
                    size_t o1 = ((size_t)bB * 64 + h + 1) * 2048 + tl;
                    g_k16[o0]     = h16(v0); g_k16[o1]     = h16(v1);
                    g_k16[o0 + 8] = h16(v2); g_k16[o1 + 8] = h16(v3);
                } else if (mat == 1) {            // Q scaled
                    *(u32*)&g_q16[(size_t)tok * 64 + h] = cvt2h(v0 * QSC, v1 * QSC);
                    *(u32*)&g_q16[(size_t)(tok + 8) * 64 + h] = cvt2h(v2 * QSC, v3 * QSC);
                } else {                          // V fp16
                    *(u32*)&g_v16[(size_t)tok * 64 + h] = cvt2h(v0, v1);
                    *(u32*)&g_v16[(size_t)(tok + 8) * 64 + h] = cvt2h(v2, v3);
                }
            }
        }
    }
}

// ---------------------------------------------------------------------------
// attention: 256 threads, 8 warps (mw 0..3 x nw 0..1), one q-tile (64) per
// block. KV macro-tile 128 (two 64-kv sub-steps per barrier round).
// grid 256, 2 blocks/SM; big+small interleave. exp via ex2.approx.f16x2.
// smem: Q 8K + 2 x {Ksub0 8K, Ksub1 8K, Vsub0 8K, Vsub1 8K} = 72K
// ---------------------------------------------------------------------------
#define A_Q   0
#define A_BUF 8192
#define A_BSZ 32768
#define A_TOT (A_BUF + 2 * A_BSZ)   // 73728
#define A_RED A_BUF
#define A_LRED (A_BUF + 64 * 68 * 4)

__global__ void __launch_bounds__(256, 2) attn_kernel(float* __restrict__ out)
{
    extern __shared__ char smem[];
    const u32 sb = smem_u32(smem);
    const int tid = threadIdx.x;
    const int lane = tid & 31;
    const int wid = tid >> 5;
    const int mw = wid & 3, nw = wid >> 2;
    const int g = lane >> 2, tg = lane & 3;
    const int ln15 = lane & 15, l16 = lane >> 4;
    const int bid = blockIdx.x;
    const int qt = (bid < 128) ? (31 - (bid >> 3)) : ((bid - 128) >> 3);
    const int b  = bid & 7;
    const int q0 = qt * 64;
    const int kvend = q0 + 64;
    const int nt = (qt + 2) >> 1;               // 128-kv macro tiles

    const u16* Kg = g_k16 + (size_t)b * 64 * 2048;
    const u16* Vg = g_v16 + (size_t)b * 2048 * 64;

    // load Q (fp16, log2e-folded)
#pragma unroll
    for (int i = 0; i < 2; i++) {
        int idx = tid + i * 256;
        int r = idx >> 3, c8 = idx & 7;
        const u16* src = g_q16 + (size_t)(b * 2048 + q0 + r) * 64 + c8 * 8;
        uint4 v = *(const uint4*)src;
        *(uint4*)(smem + A_Q + swa(0, r, c8)) = v;
    }

    // prologue: async macro-tile 0 (K sub0/sub1, V sub0/sub1)
#pragma unroll
    for (int i = 0; i < 8; i++) {
        int idx = tid + i * 256;                // < 2048
        int arr = idx >> 9;                     // 0..3
        int rem = idx & 511;
        int r = rem >> 3, c8 = rem & 7;
        const u16* src;
        u32 dst = A_BUF;
        if (arr < 2) { src = Kg + (size_t)r * 2048 + arr * 64 + c8 * 8; dst += arr * 8192; }
        else { int s = arr - 2; src = Vg + (size_t)(s * 64 + r) * 64 + c8 * 8; dst += 16384 + s * 8192; }
        cpa16(sb + swa(dst, r, c8), src);
    }
    CP_COMMIT();

    float S[4][4], O[8][4];
    float l0 = 0.f, l1 = 0.f;
#pragma unroll
    for (int j = 0; j < 8; j++)
#pragma unroll
        for (int r = 0; r < 4; r++) O[j][r] = 0.f;

    u32 qf[4][4];
    bool qloaded = false;

    for (int t = 0; t < nt; t++) {
        CP_WAIT0();
        __syncthreads();

        // prefetch macro-tile t+1 into the other slot
        if (t + 1 < nt) {
            const int kvn = (t + 1) * 128;
            const u32 bufn = A_BUF + ((t + 1) & 1) * A_BSZ;
#pragma unroll
            for (int i = 0; i < 8; i++) {
                int idx = tid + i * 256;
                int arr = idx >> 9;
                int rem = idx & 511;
                int r = rem >> 3, c8 = rem & 7;
                const u16* src;
                u32 dst = bufn;
                if (arr < 2) { src = Kg + (size_t)r * 2048 + kvn + arr * 64 + c8 * 8; dst += arr * 8192; }
                else { int s = arr - 2; src = Vg + (size_t)(kvn + s * 64 + r) * 64 + c8 * 8; dst += 16384 + s * 8192; }
                cpa16(sb + swa(dst, r, c8), src);
            }
            CP_COMMIT();
        }

        if (!qloaded) {
            qloaded = true;
#pragma unroll
            for (int ks = 0; ks < 4; ks++)
                ldsm4(qf[ks][0], qf[ks][1], qf[ks][2], qf[ks][3],
                      swa(sb + A_Q, 16 * mw + ln15, 2 * ks + l16));
        }

        const u32 buf = sb + A_BUF + (t & 1) * A_BSZ;

#pragma unroll
        for (int sub = 0; sub < 2; sub++) {
            const int kv0 = t * 128 + sub * 64;
            if (kv0 >= kvend) break;
            const u32 KT = buf + sub * 8192;
            const u32 VT = buf + 16384 + sub * 8192;

            // S slice 16x32 (kv cols nw*32..+31 within this 64-kv sub-tile)
#pragma unroll
            for (int j = 0; j < 4; j++)
#pragma unroll
                for (int r = 0; r < 4; r++) S[j][r] = 0.f;
#pragma unroll
            for (int ks = 0; ks < 4; ks++) {
#pragma unroll
                for (int p = 0; p < 2; p++) {
                    u32 b0, b1, b2, b3;
                    ldsm4t(b0, b1, b2, b3,
                           swa(KT, 16 * ks + ln15, nw * 4 + 2 * p + l16));
                    mma16816(S[2 * p],     qf[ks], b0, b1);
                    mma16816(S[2 * p + 1], qf[ks], b2, b3);
                }
            }

            // p = 2^s (f16x2); mask on diagonal sub-tile; accumulate l
            const bool diag = (kv0 == q0);
            const int rl0 = 16 * mw + g;
            u32 ph[2][4];
#pragma unroll
            for (int j = 0; j < 4; j++) {
                int col0 = nw * 32 + 8 * j + 2 * tg;
                u32 p0 = ex2h2(cvt2h(S[j][0], S[j][1]));
                u32 p1 = ex2h2(cvt2h(S[j][2], S[j][3]));
                if (diag) {
                    u32 m0 = (col0 <= rl0 ? 0xFFFFu : 0u) | (col0 + 1 <= rl0 ? 0xFFFF0000u : 0u);
                    u32 m1 = (col0 <= rl0 + 8 ? 0xFFFFu : 0u) | (col0 + 1 <= rl0 + 8 ? 0xFFFF0000u : 0u);
                    p0 &= m0;
                    p1 &= m1;
                }
                l0 += hsum2(p0);
                l1 += hsum2(p1);
                ph[j >> 1][(j & 1) * 2]     = p0;
                ph[j >> 1][(j & 1) * 2 + 1] = p1;
            }

            // O += P @ V over warp's 32 kv rows
#pragma unroll
            for (int ks = 0; ks < 2; ks++) {
                int vr = nw * 32 + 16 * ks + ln15;
#pragma unroll
                for (int gh = 0; gh < 4; gh++) {
                    u32 b0, b1, b2, b3;
                    ldsm4t(b0, b1, b2, b3, swa(VT, vr, 2 * gh + l16));
                    mma16816(O[2 * gh],     ph[ks], b0, b1);
                    mma16816(O[2 * gh + 1], ph[ks], b2, b3);
                }
            }
        }
    }

    __syncthreads();                  // compute done before scratch reuse

    // reduce l across 4 lanes sharing a row
    l0 += __shfl_xor_sync(0xffffffffu, l0, 1);
    l0 += __shfl_xor_sync(0xffffffffu, l0, 2);
    l1 += __shfl_xor_sync(0xffffffffu, l1, 1);
    l1 += __shfl_xor_sync(0xffffffffu, l1, 2);

    // cross-nw reduction via smem (aliases KV buffers)
    float* RED  = (float*)(smem + A_RED);
    float* LRED = (float*)(smem + A_LRED);
    const int r0 = 16 * mw + g;
    if (nw == 1) {
#pragma unroll
        for (int j = 0; j < 8; j++) {
            int col = 8 * j + 2 * tg;
            RED[r0 * 68 + col]           = O[j][0];
            RED[r0 * 68 + col + 1]       = O[j][1];
            RED[(r0 + 8) * 68 + col]     = O[j][2];
            RED[(r0 + 8) * 68 + col + 1] = O[j][3];
        }
        if (tg == 0) { LRED[r0] = l0; LRED[r0 + 8] = l1; }
    }
    __syncthreads();
    if (nw == 0) {
        float inv0 = 1.f / (l0 + LRED[r0]);
        float inv1 = 1.f / (l1 + LRED[r0 + 8]);
        float* O0 = out + ((size_t)b * T_ + q0 + r0) * H_;
        float* O1 = O0 + 8 * H_;
#pragma unroll
        for (int j = 0; j < 8; j++) {
            int col = 8 * j + 2 * tg;
            *(float2*)&O0[col] = make_float2(
                (O[j][0] + RED[r0 * 68 + col]) * inv0,
                (O[j][1] + RED[r0 * 68 + col + 1]) * inv0);
            *(float2*)&O1[col] = make_float2(
                (O[j][2] + RED[(r0 + 8) * 68 + col]) * inv1,
                (O[j][3] + RED[(r0 + 8) * 68 + col + 1]) * inv1);
        }
    }
}

// ---------------------------------------------------------------------------
extern "C" void kernel_launch(void* const* d_in, const int* in_sizes, int n_in,
                              void* d_out, int out_size)
{
    const float* x  = (const float*)d_in[0];
    const float* Wk = (const float*)d_in[1];
    const float* Wq = (const float*)d_in[2];
    const float* Wv = (const float*)d_in[3];
    float* out = (float*)d_out;
    (void)in_sizes; (void)n_in; (void)out_size;

    cudaFuncSetAttribute(proj_kernel,
                         cudaFuncAttributeMaxDynamicSharedMemorySize, P_TOT);
    cudaFuncSetAttribute(attn_kernel,
                         cudaFuncAttributeMaxDynamicSharedMemorySize, A_TOT);

    prep_w_kernel<<<192, 256>>>(Wk, Wq, Wv);
    proj_kernel<<<BT_ / 64, 256, P_TOT>>>(x);
    attn_kernel<<<256, 256, A_TOT>>>(out);
}